// round 7
// baseline (speedup 1.0000x reference)
#include <cuda_runtime.h>
#include <cuda_fp16.h>
#include <cstdint>

#define Nn 100000
#define Mm 800000
#define FIN 64
#define FE  16
#define HH  64
#define CAP 48

// ---------------- device scratch (no allocations allowed) ----------------
__device__ __half  g_h2h[(size_t)Nn * 64];    // h2 rows fp16 (128B/row)
__device__ float4  g_aggE[Nn * 12];           // aggregated edge_feat [N][3][16]
__device__ float   g_cntE[Nn * 3];            // per (dst, etype) counts
__device__ int     g_cur[Nn];                 // bucket cursors
__device__ int     g_slots[(size_t)Nn * CAP]; // bucket payload: src per incident edge
__device__ int     g_ovf_cnt;
__device__ int2    g_ovf[8192];               // overflow edges (src,dst)

__device__ __forceinline__ void red_add_f4(float4* p, float4 v) {
    asm volatile("red.global.add.v4.f32 [%0], {%1,%2,%3,%4};"
                 :: "l"(p), "f"(v.x), "f"(v.y), "f"(v.z), "f"(v.w)
                 : "memory");
}

__device__ __forceinline__ void mma_f16(float c[4], uint32_t a0, uint32_t a1,
                                        uint32_t a2, uint32_t a3,
                                        uint32_t b0, uint32_t b1) {
    asm volatile(
        "mma.sync.aligned.m16n8k16.row.col.f32.f16.f16.f32 "
        "{%0,%1,%2,%3},{%4,%5,%6,%7},{%8,%9},{%0,%1,%2,%3};"
        : "+f"(c[0]), "+f"(c[1]), "+f"(c[2]), "+f"(c[3])
        : "r"(a0), "r"(a1), "r"(a2), "r"(a3), "r"(b0), "r"(b1));
}

__device__ __forceinline__ uint32_t pack_h2(float a, float b) {
    __half2 h = __floats2half2_rn(a, b);
    return *(uint32_t*)&h;
}

// ---------------- kernels ----------------

__global__ void zero_kernel() {
    int gid = blockIdx.x * blockDim.x + threadIdx.x;
    int stride = gridDim.x * blockDim.x;
    float4 z = make_float4(0.f, 0.f, 0.f, 0.f);
    for (int i = gid; i < Nn * 12; i += stride) g_aggE[i] = z;
    for (int i = gid; i < Nn * 3; i += stride) g_cntE[i] = 0.f;
    for (int i = gid; i < Nn; i += stride) g_cur[i] = 0;
    if (gid == 0) g_ovf_cnt = 0;
}

// 4 threads/edge: scatter-add ef into aggE[dst][etype]; fused count + bucket fill
__global__ void edge_scatter_kernel(const float* __restrict__ ef,
                                    const int* __restrict__ esrc,
                                    const int* __restrict__ edst,
                                    const int* __restrict__ etype) {
    int gid = blockIdx.x * blockDim.x + threadIdx.x;
    int e = gid >> 2, q = gid & 3;
    if (e >= Mm) return;
    int dst = edst[e];
    int t   = etype[e];
    float4 v = ((const float4*)ef)[e * 4 + q];
    red_add_f4(&g_aggE[dst * 12 + t * 4 + q], v);
    if (q == 0) {
        atomicAdd(&g_cntE[dst * 3 + t], 1.0f);
        int src = esrc[e];
        int p = atomicAdd(&g_cur[dst], 1);
        if (p < CAP) {
            g_slots[(size_t)dst * CAP + p] = src;
        } else {
            int o = atomicAdd(&g_ovf_cnt, 1);
            if (o < 8192) g_ovf[o] = make_int2(src, dst);
        }
    }
}

// Persistent node GEMM (fp16 m16n8k16), 512 threads, tile M=64, NATURAL node
// order (fully coalesced). Computes BOTH node types; epilogue stores the
// matching type's columns only.
// A[64 x 128] = [x(64) | aggE(48) | cnt(3) | 0(13)] fp16, xs2[row][k2] stride 68.
// B[120 x 256] = type0{[W1|W2],[W5|0],[b5|0]} | type1{...}, fragment order:
//   Wf[cgf(4)][kb(8)][ntp(4)][lane(32)] uint4 -> per-warp B ops are LDS.128.
// Warp w: row group (w&3)*16, col group (w>>2)*64. typ=cgf>>1, h1/h2=cgf&1.
#define XSTR 68
__global__ __launch_bounds__(512, 1)
void node_gemm_kernel(const float* __restrict__ x,
                      const int* __restrict__ ntype,
                      const float* __restrict__ W1, const float* __restrict__ b1,
                      const float* __restrict__ W2, const float* __restrict__ b2,
                      const float* __restrict__ W5, const float* __restrict__ b5,
                      float* __restrict__ out) {
    extern __shared__ uint32_t smu[];
    uint4* Wf = (uint4*)smu;                 // 4096 uint4 = 16384 words
    uint32_t* xs2 = smu + 16384;             // [64][68] half2 words
    float* bc = (float*)(xs2 + 64 * XSTR);   // [256]
    int* stype = (int*)(bc + 256);           // [64]

    const int tid = threadIdx.x;
    const int w = tid >> 5, lane = tid & 31;
    const int g = lane >> 2, tq = lane & 3;
    const int rbase = (w & 3) * 16;          // 4 row groups
    const int cgf = w >> 2;                  // 4 col groups of 64
    const int typ = cgf >> 1;                // which node type this warp serves
    const int isH2 = cgf & 1;                // 0 -> out, 1 -> g_h2h
    const int r = tid >> 3, sub = tid & 7;   // A staging: 8 threads per row

    const int tiles = (Nn + 63) >> 6;

    // zero A tile (pad k2 58..67 stays zero forever)
    for (int i = tid; i < 64 * XSTR; i += 512) xs2[i] = 0;

    // ---- one-time B fill (both types), fragment order ----
    {
        auto w_src = [&](int kk, int c) -> float {
            int ty = c >> 7;            // 0 or 1
            int wh = (c >> 6) & 1;      // 0 = h1 cols, 1 = h2 cols
            int cc = c & 63;
            float v = 0.f;
            if (kk < 64) {
                v = wh ? W2[ty * (FIN * HH) + kk * 64 + cc]
                       : W1[ty * (FIN * HH) + kk * 64 + cc];
            } else if (kk < 112) { if (!wh) v = W5[(kk - 64) * 64 + cc]; }
            else if (kk < 115)   { if (!wh) v = b5[(kk - 112) * 64 + cc]; }
            return v;
        };
        for (int idx = tid; idx < 4096; idx += 512) {
            int ln = idx & 31;
            int ntp = (idx >> 5) & 3;
            int kb = (idx >> 7) & 7;
            int cg = idx >> 10;                 // 0..3
            int tqf = ln & 3, gf = ln >> 2;
            int k2a = kb * 8 + tqf;
            int k2b = kb * 8 + tqf + 4;
            int col0 = cg * 64 + (2 * ntp) * 8 + gf;
            int col1 = col0 + 8;
            uint4 wv;
            wv.x = pack_h2(w_src(2 * k2a, col0), w_src(2 * k2a + 1, col0));
            wv.y = pack_h2(w_src(2 * k2b, col0), w_src(2 * k2b + 1, col0));
            wv.z = pack_h2(w_src(2 * k2a, col1), w_src(2 * k2a + 1, col1));
            wv.w = pack_h2(w_src(2 * k2b, col1), w_src(2 * k2b + 1, col1));
            Wf[idx] = wv;
        }
        if (tid < 256) {
            int ty = tid >> 7, wh = (tid >> 6) & 1, cc = tid & 63;
            bc[tid] = wh ? b2[ty * 64 + cc] : b1[ty * 64 + cc];
        }
    }

    // register staging (coalesced loads, half2-packed)
    uint2 hx[2], ha[2];
    uint32_t hcnt01 = 0, hcnt2 = 0;
    int stp = -1;

    auto stage_load = [&](int tile) {
        int node = tile * 64 + r;
        if (node < Nn) {
            const float4* x4 = (const float4*)x;
            {
                float4 v = x4[node * 16 + sub];
                hx[0] = make_uint2(pack_h2(v.x, v.y), pack_h2(v.z, v.w));
                v = x4[node * 16 + sub + 8];
                hx[1] = make_uint2(pack_h2(v.x, v.y), pack_h2(v.z, v.w));
            }
            {
                float4 v = g_aggE[node * 12 + sub];
                ha[0] = make_uint2(pack_h2(v.x, v.y), pack_h2(v.z, v.w));
                if (sub < 4) {
                    v = g_aggE[node * 12 + sub + 8];
                    ha[1] = make_uint2(pack_h2(v.x, v.y), pack_h2(v.z, v.w));
                }
            }
            if (sub == 7) {
                float c0 = g_cntE[node * 3 + 0];
                float c1 = g_cntE[node * 3 + 1];
                float c2 = g_cntE[node * 3 + 2];
                hcnt01 = pack_h2(c0, c1);
                hcnt2 = pack_h2(c2, 0.f);
            }
            if (sub == 6) stp = ntype[node];
        } else {
            uint2 z = make_uint2(0u, 0u);
            hx[0] = hx[1] = ha[0] = ha[1] = z;
            hcnt01 = 0; hcnt2 = 0;
            stp = -1;
        }
    };

    auto stage_store = [&]() {
        uint32_t* row = xs2 + r * XSTR;
        *(uint2*)(row + 2 * sub) = hx[0];          // k2 2sub,2sub+1
        *(uint2*)(row + 2 * sub + 16) = hx[1];     // k2 16+2sub
        *(uint2*)(row + 32 + 2 * sub) = ha[0];     // k2 32+2sub
        if (sub < 4) *(uint2*)(row + 48 + 2 * sub) = ha[1];
        if (sub == 7) { row[56] = hcnt01; row[57] = hcnt2; }
        if (sub == 6) stype[r] = stp;
    };

    stage_load(blockIdx.x);

    for (int tile = blockIdx.x; tile < tiles; tile += gridDim.x) {
        __syncthreads();   // prior tile's readers done / init done
        stage_store();
        __syncthreads();

        int next = tile + gridDim.x;
        if (next < tiles) stage_load(next);   // LDGs overlap MMA below

        float acc[8][4];
        #pragma unroll
        for (int nt = 0; nt < 8; nt++)
            #pragma unroll
            for (int j = 0; j < 4; j++) acc[nt][j] = 0.f;

        const uint4* Wfw = Wf + cgf * 1024;
        #pragma unroll
        for (int kb = 0; kb < 8; kb++) {
            int kb2 = kb * 8;
            uint32_t a0 = xs2[(rbase + g) * XSTR + kb2 + tq];
            uint32_t a1 = xs2[(rbase + g + 8) * XSTR + kb2 + tq];
            uint32_t a2 = xs2[(rbase + g) * XSTR + kb2 + tq + 4];
            uint32_t a3 = xs2[(rbase + g + 8) * XSTR + kb2 + tq + 4];
            #pragma unroll
            for (int ntp = 0; ntp < 4; ntp++) {
                uint4 bw = Wfw[(kb * 4 + ntp) * 32 + lane];
                mma_f16(acc[2 * ntp], a0, a1, a2, a3, bw.x, bw.y);
                mma_f16(acc[2 * ntp + 1], a0, a1, a2, a3, bw.z, bw.w);
            }
        }

        __half2* h2p = (__half2*)g_h2h;
        float2* outp = (float2*)out;
        #pragma unroll
        for (int half_r = 0; half_r < 2; half_r++) {
            int rr = rbase + g + half_r * 8;
            if (stype[rr] != typ) continue;    // other type / out-of-range
            int node = tile * 64 + rr;
            #pragma unroll
            for (int nt = 0; nt < 8; nt++) {
                int col0 = nt * 8 + 2 * tq;    // 0..63 within group
                float v0 = acc[nt][half_r * 2 + 0] + bc[cgf * 64 + col0];
                float v1 = acc[nt][half_r * 2 + 1] + bc[cgf * 64 + col0 + 1];
                if (!isH2) {
                    outp[node * 32 + (col0 >> 1)] = make_float2(v0, v1);
                } else {
                    h2p[node * 32 + (col0 >> 1)] = __floats2half2_rn(v0, v1);
                }
            }
        }
    }
}

// Bucket gather: out[dst] += sum_{incident} h2[src]; 16 lanes per node
__global__ __launch_bounds__(256)
void h2_gather_kernel(float* __restrict__ out) {
    int tid = threadIdx.x;
    int node = blockIdx.x * 16 + (tid >> 4);
    int q = tid & 15;
    if (node >= Nn) return;
    int deg = g_cur[node];
    if (deg > CAP) deg = CAP;
    if (deg == 0) return;

    const uint2* H = (const uint2*)g_h2h;
    const int* sl = &g_slots[(size_t)node * CAP];
    float4 acc = make_float4(0.f, 0.f, 0.f, 0.f);

    auto add4 = [&](uint2 hv) {
        float2 f0 = __half22float2(*(__half2*)&hv.x);
        float2 f1 = __half22float2(*(__half2*)&hv.y);
        acc.x += f0.x; acc.y += f0.y; acc.z += f1.x; acc.w += f1.y;
    };

    int i = 0;
    for (; i + 4 <= deg; i += 4) {
        int s0 = __ldg(&sl[i]);
        int s1 = __ldg(&sl[i + 1]);
        int s2 = __ldg(&sl[i + 2]);
        int s3 = __ldg(&sl[i + 3]);
        uint2 v0 = __ldg(&H[s0 * 16 + q]);
        uint2 v1 = __ldg(&H[s1 * 16 + q]);
        uint2 v2 = __ldg(&H[s2 * 16 + q]);
        uint2 v3 = __ldg(&H[s3 * 16 + q]);
        add4(v0); add4(v1); add4(v2); add4(v3);
    }
    for (; i < deg; i++) add4(__ldg(&H[__ldg(&sl[i]) * 16 + q]));

    float4* o4 = (float4*)out;
    float4 o = o4[node * 16 + q];
    o.x += acc.x; o.y += acc.y; o.z += acc.z; o.w += acc.w;
    o4[node * 16 + q] = o;
}

// Rare overflow edges (deg > CAP): atomic scatter
__global__ void ovf_kernel(float4* __restrict__ out) {
    int n = g_ovf_cnt;
    if (n > 8192) n = 8192;
    int stride = gridDim.x * blockDim.x;
    for (int i = blockIdx.x * blockDim.x + threadIdx.x; i < n * 16; i += stride) {
        int e = i >> 4, q = i & 15;
        int2 sd = g_ovf[e];
        uint2 hv = ((const uint2*)g_h2h)[sd.x * 16 + q];
        float2 f0 = __half22float2(*(__half2*)&hv.x);
        float2 f1 = __half22float2(*(__half2*)&hv.y);
        red_add_f4(&out[sd.y * 16 + q], make_float4(f0.x, f0.y, f1.x, f1.y));
    }
}

// ---------------- launch ----------------
extern "C" void kernel_launch(void* const* d_in, const int* in_sizes, int n_in,
                              void* d_out, int out_size) {
    const float *x = nullptr, *ef = nullptr;
    const float *W[4] = {nullptr, nullptr, nullptr, nullptr};
    const float *B[4] = {nullptr, nullptr, nullptr, nullptr};
    const float *W5 = nullptr, *b5 = nullptr;
    const int *ntype = nullptr, *esrc = nullptr, *edst = nullptr, *etype = nullptr;
    int wI = 0, bI = 0, mI = 0;
    for (int i = 0; i < n_in; i++) {
        long s = in_sizes[i];
        const void* p = d_in[i];
        if (s == (long)Nn * FIN)      x = (const float*)p;
        else if (s == (long)Mm * FE)  ef = (const float*)p;
        else if (s == Nn)             ntype = (const int*)p;
        else if (s == Mm) {
            if (mI == 0) esrc = (const int*)p;
            else if (mI == 1) edst = (const int*)p;
            else etype = (const int*)p;
            mI++;
        }
        else if (s == 2 * FIN * HH) { if (wI < 4) W[wI++] = (const float*)p; }
        else if (s == 2 * HH)       { if (bI < 4) B[bI++] = (const float*)p; }
        else if (s == 3 * FE * HH)  W5 = (const float*)p;
        else if (s == 3 * HH)       b5 = (const float*)p;
    }
    float* out = (float*)d_out;

    const int smem_bytes = (16384 + 64 * XSTR + 256) * 4 + 64 * 4;
    cudaFuncSetAttribute(node_gemm_kernel,
                         cudaFuncAttributeMaxDynamicSharedMemorySize, 100 * 1024);

    zero_kernel<<<2048, 256>>>();
    edge_scatter_kernel<<<(Mm * 4 + 255) / 256, 256>>>(ef, esrc, edst, etype);
    node_gemm_kernel<<<148, 512, smem_bytes>>>(
        x, ntype, W[0], B[0], W[1], B[1], W5, b5, out);
    h2_gather_kernel<<<(Nn + 15) / 16, 256>>>(out);
    ovf_kernel<<<16, 256>>>((float4*)out);
}

// round 8
// speedup vs baseline: 1.0732x; 1.0732x over previous
#include <cuda_runtime.h>
#include <cuda_fp16.h>
#include <cstdint>

#define Nn 100000
#define Mm 800000
#define FIN 64
#define FE  16
#define HH  64
#define CAP 48

// ---------------- device scratch (no allocations allowed) ----------------
__device__ __half  g_h2h[(size_t)Nn * 64];    // h2 rows fp16 (128B/row)
__device__ float4  g_aggE[Nn * 12];           // aggregated edge_feat [N][3][16]
__device__ int     g_cur[Nn];                 // packed: tot(10) | c1(10) | c2(10)
__device__ int     g_slots[(size_t)Nn * CAP]; // bucket payload: src per edge
__device__ int     g_ovf_cnt;
__device__ int2    g_ovf[8192];               // overflow edges (src,dst)

__device__ __forceinline__ void red_add_f4(float4* p, float4 v) {
    asm volatile("red.global.add.v4.f32 [%0], {%1,%2,%3,%4};"
                 :: "l"(p), "f"(v.x), "f"(v.y), "f"(v.z), "f"(v.w)
                 : "memory");
}

__device__ __forceinline__ void mma_f16(float c[4], uint32_t a0, uint32_t a1,
                                        uint32_t a2, uint32_t a3,
                                        uint32_t b0, uint32_t b1) {
    asm volatile(
        "mma.sync.aligned.m16n8k16.row.col.f32.f16.f16.f32 "
        "{%0,%1,%2,%3},{%4,%5,%6,%7},{%8,%9},{%0,%1,%2,%3};"
        : "+f"(c[0]), "+f"(c[1]), "+f"(c[2]), "+f"(c[3])
        : "r"(a0), "r"(a1), "r"(a2), "r"(a3), "r"(b0), "r"(b1));
}

__device__ __forceinline__ uint32_t pack_h2(float a, float b) {
    __half2 h = __floats2half2_rn(a, b);
    return *(uint32_t*)&h;
}

// ---------------- kernels ----------------

__global__ void zero_kernel() {
    int gid = blockIdx.x * blockDim.x + threadIdx.x;
    int stride = gridDim.x * blockDim.x;
    float4 z = make_float4(0.f, 0.f, 0.f, 0.f);
    for (int i = gid; i < Nn * 12; i += stride) g_aggE[i] = z;
    for (int i = gid; i < Nn; i += stride) g_cur[i] = 0;
    if (gid == 0) g_ovf_cnt = 0;
}

// 4 threads/edge: scatter-add ef into aggE[dst][etype]; ONE packed int atomic
// carries total count, per-type counts, and the bucket cursor.
__global__ void edge_scatter_kernel(const float* __restrict__ ef,
                                    const int* __restrict__ esrc,
                                    const int* __restrict__ edst,
                                    const int* __restrict__ etype) {
    int gid = blockIdx.x * blockDim.x + threadIdx.x;
    int e = gid >> 2, q = gid & 3;
    if (e >= Mm) return;
    int dst = edst[e];
    int t   = etype[e];
    float4 v = ((const float4*)ef)[e * 4 + q];
    red_add_f4(&g_aggE[dst * 12 + t * 4 + q], v);
    if (q == 0) {
        int inc = 1 + ((t == 1) ? (1 << 10) : 0) + ((t == 2) ? (1 << 20) : 0);
        int old = atomicAdd(&g_cur[dst], inc);
        int p = old & 1023;
        int src = esrc[e];
        if (p < CAP) {
            g_slots[(size_t)dst * CAP + p] = src;
        } else {
            int o = atomicAdd(&g_ovf_cnt, 1);
            if (o < 8192) g_ovf[o] = make_int2(src, dst);
        }
    }
}

// Warp-autonomous node GEMM (fp16 m16n8k16). No barriers in the main loop.
// Each warp owns 16 consecutive nodes; A-fragments (k=128) live in registers,
// loaded directly from global. B (both types, h1|h2) is block-shared smem in
// fragment order: Wf[cgf(4)][kb(8)][ntp(4)][lane(32)] uint4 (LDS.128 loads).
// A row k-layout: [x(64) | aggE(48) | cnt(3) | 0(13)].
// cgf: 0=type0->out, 1=type0->h2, 2=type1->out, 3=type1->h2.
__global__ __launch_bounds__(256, 2)
void node_gemm_kernel(const float* __restrict__ x,
                      const int* __restrict__ ntype,
                      const float* __restrict__ W1, const float* __restrict__ b1,
                      const float* __restrict__ W2, const float* __restrict__ b2,
                      const float* __restrict__ W5, const float* __restrict__ b5,
                      float* __restrict__ out) {
    extern __shared__ uint32_t smu[];
    uint4* Wf = (uint4*)smu;                 // 4096 uint4 = 64 KB
    float* bc = (float*)(smu + 16384);       // [256]

    const int tid = threadIdx.x;
    const int w = tid >> 5, lane = tid & 31;
    const int g = lane >> 2, tq = lane & 3;

    // ---- one-time B fill (both types), fragment order ----
    {
        auto w_src = [&](int kk, int c) -> float {
            int ty = c >> 7;            // type
            int wh = (c >> 6) & 1;      // 0 = h1 cols, 1 = h2 cols
            int cc = c & 63;
            float v = 0.f;
            if (kk < 64) {
                v = wh ? W2[ty * (FIN * HH) + kk * 64 + cc]
                       : W1[ty * (FIN * HH) + kk * 64 + cc];
            } else if (kk < 112) { if (!wh) v = W5[(kk - 64) * 64 + cc]; }
            else if (kk < 115)   { if (!wh) v = b5[(kk - 112) * 64 + cc]; }
            return v;
        };
        for (int idx = tid; idx < 4096; idx += 256) {
            int ln = idx & 31;
            int ntp = (idx >> 5) & 3;
            int kb = (idx >> 7) & 7;
            int cg = idx >> 10;
            int tqf = ln & 3, gf = ln >> 2;
            int k2a = kb * 8 + tqf;
            int k2b = kb * 8 + tqf + 4;
            // column index within the 256-wide B: type/h-sel from cg
            int col0 = ((cg >> 1) << 7) + ((cg & 1) << 6) + (2 * ntp) * 8 + gf;
            int col1 = col0 + 8;
            uint4 wv;
            wv.x = pack_h2(w_src(2 * k2a, col0), w_src(2 * k2a + 1, col0));
            wv.y = pack_h2(w_src(2 * k2b, col0), w_src(2 * k2b + 1, col0));
            wv.z = pack_h2(w_src(2 * k2a, col1), w_src(2 * k2a + 1, col1));
            wv.w = pack_h2(w_src(2 * k2b, col1), w_src(2 * k2b + 1, col1));
            Wf[idx] = wv;
        }
        if (tid < 256) {
            int ty = tid >> 7, wh = (tid >> 6) & 1, cc = tid & 63;
            bc[tid] = wh ? b2[ty * 64 + cc] : b1[ty * 64 + cc];
        }
    }
    __syncthreads();   // only barrier in the kernel

    const int G = (Nn + 15) >> 4;            // 16-node groups
    const int nwarps = gridDim.x << 3;
    __half2* h2p = (__half2*)g_h2h;
    float2* outp = (float2*)out;
    const float* aggf = (const float*)g_aggE;

    for (int grp = blockIdx.x * 8 + w; grp < G; grp += nwarps) {
        int base = grp << 4;

        // ---- load A fragments for rows g and g+8 into registers ----
        uint32_t ax[2][16];
        int ntp_[2];
        #pragma unroll
        for (int j = 0; j < 2; j++) {
            int node = base + g + 8 * j;
            if (node < Nn) {
                const float* xr = x + (size_t)node * 64;
                #pragma unroll
                for (int m = 0; m < 8; m++) {
                    float2 v = *(const float2*)(xr + 8 * m + 2 * tq);
                    ax[j][m] = pack_h2(v.x, v.y);
                }
                const float* ar = aggf + (size_t)node * 48;
                #pragma unroll
                for (int m = 8; m < 14; m++) {
                    float2 v = *(const float2*)(ar + 8 * (m - 8) + 2 * tq);
                    ax[j][m] = pack_h2(v.x, v.y);
                }
                int cv = __ldg(&g_cur[node]);
                int tot = cv & 1023, c1i = (cv >> 10) & 1023, c2i = cv >> 20;
                float c0 = (float)(tot - c1i - c2i);
                ax[j][14] = (tq == 0) ? pack_h2(c0, (float)c1i)
                          : (tq == 1) ? pack_h2((float)c2i, 0.f) : 0u;
                ax[j][15] = 0u;
                ntp_[j] = ntype[node];
            } else {
                #pragma unroll
                for (int m = 0; m < 16; m++) ax[j][m] = 0u;
                ntp_[j] = -1;
            }
        }

        // ---- 4 col-groups, acc regs reused ----
        #pragma unroll
        for (int cgf = 0; cgf < 4; cgf++) {
            const int typ = cgf >> 1, isH2 = cgf & 1;
            float acc[8][4];
            #pragma unroll
            for (int nt = 0; nt < 8; nt++)
                #pragma unroll
                for (int jj = 0; jj < 4; jj++) acc[nt][jj] = 0.f;

            const uint4* Wfw = Wf + cgf * 1024;
            #pragma unroll
            for (int kb = 0; kb < 8; kb++) {
                uint32_t a0 = ax[0][2 * kb];
                uint32_t a1 = ax[1][2 * kb];
                uint32_t a2 = ax[0][2 * kb + 1];
                uint32_t a3 = ax[1][2 * kb + 1];
                #pragma unroll
                for (int ntp = 0; ntp < 4; ntp++) {
                    uint4 bw = Wfw[(kb * 4 + ntp) * 32 + lane];
                    mma_f16(acc[2 * ntp], a0, a1, a2, a3, bw.x, bw.y);
                    mma_f16(acc[2 * ntp + 1], a0, a1, a2, a3, bw.z, bw.w);
                }
            }

            #pragma unroll
            for (int j = 0; j < 2; j++) {
                if (ntp_[j] != typ) continue;
                int node = base + g + 8 * j;
                #pragma unroll
                for (int nt = 0; nt < 8; nt++) {
                    int col0 = nt * 8 + 2 * tq;
                    float v0 = acc[nt][2 * j + 0] + bc[cgf * 64 + col0];
                    float v1 = acc[nt][2 * j + 1] + bc[cgf * 64 + col0 + 1];
                    if (!isH2) outp[node * 32 + (col0 >> 1)] = make_float2(v0, v1);
                    else h2p[node * 32 + (col0 >> 1)] = __floats2half2_rn(v0, v1);
                }
            }
        }
    }
}

// Bucket gather: out[dst] += sum_{incident} h2[src]; 16 lanes per node.
__global__ __launch_bounds__(256)
void h2_gather_kernel(float* __restrict__ out) {
    int tid = threadIdx.x;
    int node = blockIdx.x * 16 + (tid >> 4);
    int q = tid & 15;
    if (node >= Nn) return;
    int deg = g_cur[node] & 1023;
    if (deg > CAP) deg = CAP;
    if (deg == 0) return;

    const uint2* H = (const uint2*)g_h2h;
    const int* sl = &g_slots[(size_t)node * CAP];
    float4 acc = make_float4(0.f, 0.f, 0.f, 0.f);

    auto add4 = [&](uint2 hv) {
        float2 f0 = __half22float2(*(__half2*)&hv.x);
        float2 f1 = __half22float2(*(__half2*)&hv.y);
        acc.x += f0.x; acc.y += f0.y; acc.z += f1.x; acc.w += f1.y;
    };

    int i = 0;
    for (; i + 8 <= deg; i += 8) {
        int s[8];
        #pragma unroll
        for (int u = 0; u < 8; u++) s[u] = __ldg(&sl[i + u]);
        uint2 v[8];
        #pragma unroll
        for (int u = 0; u < 8; u++) v[u] = __ldg(&H[s[u] * 16 + q]);
        #pragma unroll
        for (int u = 0; u < 8; u++) add4(v[u]);
    }
    for (; i + 4 <= deg; i += 4) {
        int s[4];
        #pragma unroll
        for (int u = 0; u < 4; u++) s[u] = __ldg(&sl[i + u]);
        uint2 v[4];
        #pragma unroll
        for (int u = 0; u < 4; u++) v[u] = __ldg(&H[s[u] * 16 + q]);
        #pragma unroll
        for (int u = 0; u < 4; u++) add4(v[u]);
    }
    for (; i < deg; i++) add4(__ldg(&H[__ldg(&sl[i]) * 16 + q]));

    float4* o4 = (float4*)out;
    float4 o = o4[node * 16 + q];
    o.x += acc.x; o.y += acc.y; o.z += acc.z; o.w += acc.w;
    o4[node * 16 + q] = o;
}

// Rare overflow edges (deg > CAP): atomic scatter
__global__ void ovf_kernel(float4* __restrict__ out) {
    int n = g_ovf_cnt;
    if (n > 8192) n = 8192;
    int stride = gridDim.x * blockDim.x;
    for (int i = blockIdx.x * blockDim.x + threadIdx.x; i < n * 16; i += stride) {
        int e = i >> 4, q = i & 15;
        int2 sd = g_ovf[e];
        uint2 hv = ((const uint2*)g_h2h)[sd.x * 16 + q];
        float2 f0 = __half22float2(*(__half2*)&hv.x);
        float2 f1 = __half22float2(*(__half2*)&hv.y);
        red_add_f4(&out[sd.y * 16 + q], make_float4(f0.x, f0.y, f1.x, f1.y));
    }
}

// ---------------- launch ----------------
extern "C" void kernel_launch(void* const* d_in, const int* in_sizes, int n_in,
                              void* d_out, int out_size) {
    const float *x = nullptr, *ef = nullptr;
    const float *W[4] = {nullptr, nullptr, nullptr, nullptr};
    const float *B[4] = {nullptr, nullptr, nullptr, nullptr};
    const float *W5 = nullptr, *b5 = nullptr;
    const int *ntype = nullptr, *esrc = nullptr, *edst = nullptr, *etype = nullptr;
    int wI = 0, bI = 0, mI = 0;
    for (int i = 0; i < n_in; i++) {
        long s = in_sizes[i];
        const void* p = d_in[i];
        if (s == (long)Nn * FIN)      x = (const float*)p;
        else if (s == (long)Mm * FE)  ef = (const float*)p;
        else if (s == Nn)             ntype = (const int*)p;
        else if (s == Mm) {
            if (mI == 0) esrc = (const int*)p;
            else if (mI == 1) edst = (const int*)p;
            else etype = (const int*)p;
            mI++;
        }
        else if (s == 2 * FIN * HH) { if (wI < 4) W[wI++] = (const float*)p; }
        else if (s == 2 * HH)       { if (bI < 4) B[bI++] = (const float*)p; }
        else if (s == 3 * FE * HH)  W5 = (const float*)p;
        else if (s == 3 * HH)       b5 = (const float*)p;
    }
    float* out = (float*)d_out;

    const int smem_bytes = 16384 * 4 + 256 * 4;   // 66560
    cudaFuncSetAttribute(node_gemm_kernel,
                         cudaFuncAttributeMaxDynamicSharedMemorySize, 68 * 1024);

    zero_kernel<<<2048, 256>>>();
    edge_scatter_kernel<<<(Mm * 4 + 255) / 256, 256>>>(ef, esrc, edst, etype);
    node_gemm_kernel<<<296, 256, smem_bytes>>>(
        x, ntype, W[0], B[0], W[1], B[1], W5, b5, out);
    h2_gather_kernel<<<(Nn + 15) / 16, 256>>>(out);
    ovf_kernel<<<16, 256>>>((float4*)out);
}